// round 16
// baseline (speedup 1.0000x reference)
#include <cuda_runtime.h>
#include <cuda_fp16.h>
#include <math.h>
#include <stdint.h>

#define BATCH 4
#define SEQ   1024
#define DM    1024
#define NH    16
#define HD    64
#define BH    (BATCH*NH)

// Scratch (device globals: allocation-free per harness rules). All fp16.
__device__ __half g_rq [BATCH*SEQ*DM];
__device__ __half g_rk [BATCH*SEQ*DM];
__device__ __half g_rv [BATCH*SEQ*DM];
__device__ __half g_rWq[DM*DM];
__device__ __half g_rWk[DM*DM];
__device__ __half g_rWv[DM*DM];
__device__ __half g_rWo[DM*DM];
__device__ __half g_Qh [BATCH*NH*SEQ*HD];   // [B,H,S,hd]
__device__ __half g_Kh [BATCH*NH*SEQ*HD];   // [B,H,S,hd]
__device__ __half g_VhT[BATCH*NH*HD*SEQ];   // [B,H,hd,S]
__device__ __half g_AO [BATCH*SEQ*DM];      // [B,S,D]
__device__ float  g_PE [SEQ*HD];            // fp32 PE table

// ---------------------------------------------------------------------------
__device__ __forceinline__ uint32_t packh2(float a, float b) {
    __half2 h = __floats2half2_rn(a, b);
    return *reinterpret_cast<uint32_t*>(&h);
}

__device__ __forceinline__ float ex2(float x) {
    float r;
    asm("ex2.approx.f32 %0, %1;" : "=f"(r) : "f"(x));
    return r;
}

__device__ __forceinline__ void mma16(float* c, const uint32_t* a, const uint32_t* b) {
    asm volatile(
        "mma.sync.aligned.m16n8k16.row.col.f32.f16.f16.f32 "
        "{%0,%1,%2,%3},{%4,%5,%6,%7},{%8,%9},{%0,%1,%2,%3};"
        : "+f"(c[0]), "+f"(c[1]), "+f"(c[2]), "+f"(c[3])
        : "r"(a[0]), "r"(a[1]), "r"(a[2]), "r"(a[3]), "r"(b[0]), "r"(b[1]));
}

__device__ __forceinline__ void cpasync16(uint32_t dst, const void* src) {
    asm volatile("cp.async.cg.shared.global [%0], [%1], 16;" :: "r"(dst), "l"(src));
}
__device__ __forceinline__ void cp_commit() { asm volatile("cp.async.commit_group;"); }
template<int N>
__device__ __forceinline__ void cp_wait() {
    asm volatile("cp.async.wait_group %0;" :: "n"(N));
}

// ---------------------------------------------------------------------------
// Prep: round all GEMM operands to fp16 + build PE table. grid (4096, 8)
// ---------------------------------------------------------------------------
__global__ void prep_kernel(const float4* __restrict__ q, const float4* __restrict__ k,
                            const float4* __restrict__ v,
                            const float4* __restrict__ wq, const float4* __restrict__ wk,
                            const float4* __restrict__ wv, const float4* __restrict__ wo) {
    int i = blockIdx.x * blockDim.x + threadIdx.x;
    int z = blockIdx.y;
    if (z == 7) {
        int idx = i * 4;
        if (idx >= SEQ * HD) return;
        int s = idx >> 6;
        float4 r;
        float* rp = &r.x;
#pragma unroll
        for (int j = 0; j < 4; j++) {
            int d = (idx + j) & 63;
            int de = d & ~1;
            float div = expf(-(float)de * 0.14391156831212787f);   // ln(10000)/64
            float ang = (float)s * div;
            rp[j] = (d & 1) ? cosf(ang) : sinf(ang);
        }
        *(float4*)(g_PE + idx) = r;
        return;
    }
    const float4* src;
    __half* dst;
    int n4;
    switch (z) {
        case 0: src = q;  dst = g_rq;  n4 = BATCH*SEQ*DM/4; break;
        case 1: src = k;  dst = g_rk;  n4 = BATCH*SEQ*DM/4; break;
        case 2: src = v;  dst = g_rv;  n4 = BATCH*SEQ*DM/4; break;
        case 3: src = wq; dst = g_rWq; n4 = DM*DM/4; break;
        case 4: src = wk; dst = g_rWk; n4 = DM*DM/4; break;
        case 5: src = wv; dst = g_rWv; n4 = DM*DM/4; break;
        default:src = wo; dst = g_rWo; n4 = DM*DM/4; break;
    }
    if (i >= n4) return;
    float4 a = src[i];
    uint2 u;
    u.x = packh2(a.x, a.y);
    u.y = packh2(a.z, a.w);
    *reinterpret_cast<uint2*>(dst + 4 * i) = u;
}

// ---------------------------------------------------------------------------
// NT GEMM mainloop (fp16): acc = A[128,:] @ B[128,:]^T over K=1024.
// CTA 128x128, K-chunk 64 halfs (128B rows), 3-stage cp.async ring (16 iters).
// 8 warps 4(m)x2(n), warp tile 32x64, mma m16n8k16.
// 128B rows, 16B-chunk XOR key row&7 -> fragment LDS.32 conflict-free.
// Dynamic smem: A 3x16KB | B 3x16KB = 96KB. (Proven R13 config.)
// ---------------------------------------------------------------------------
#define GEMM_SMEM_BYTES 98304

__device__ __forceinline__ void gemm_mainloop_h(
    const __half* __restrict__ A, const __half* __restrict__ B,
    int cm, int cn, float acc[2][8][4])
{
    extern __shared__ __half dsm[];
    __half* As = dsm;               // 3 x 8192 halfs
    __half* Bs = dsm + 3 * 8192;

    constexpr int KT = 16;   // 1024 / 64

    const int tid = threadIdx.x;
    const int r   = tid >> 1;          // 0..127
    const int hh  = tid & 1;           // half of 128B row

    const __half* gA = A + (size_t)(cm + r) * 1024 + hh * 32;
    const __half* gB = B + (size_t)(cn + r) * 1024 + hh * 32;

    const uint32_t uA = (uint32_t)__cvta_generic_to_shared(As);
    const uint32_t uB = (uint32_t)__cvta_generic_to_shared(Bs);
    uint32_t so[4];
#pragma unroll
    for (int i = 0; i < 4; i++)
        so[i] = (uint32_t)(r * 128 + (((4 * hh + i) ^ (r & 7)) << 4));

    const int wid  = tid >> 5;
    const int lane = tid & 31;
    const int gid  = lane >> 2;
    const int tg   = lane & 3;
    const int wm = (wid & 3) * 32;
    const int wn = (wid >> 2) * 64;

    int ck[8];
#pragma unroll
    for (int j = 0; j < 8; j++) ck[j] = ((j ^ gid) << 4);
    const int baseA0 = (wm + gid) * 128 + tg * 4;
    const int baseB0 = (wn + gid) * 128 + tg * 4;

#pragma unroll
    for (int i = 0; i < 2; i++)
#pragma unroll
        for (int j = 0; j < 8; j++)
#pragma unroll
            for (int l = 0; l < 4; l++) acc[i][j][l] = 0.f;

    // prologue: stages 0,1
#pragma unroll
    for (int s = 0; s < 2; s++) {
        const uint32_t sb = (uint32_t)(s * 16384);
#pragma unroll
        for (int i = 0; i < 4; i++) {
            cpasync16(uA + sb + so[i], gA + s * 64 + i * 8);
            cpasync16(uB + sb + so[i], gB + s * 64 + i * 8);
        }
        cp_commit();
    }

    int stage = 0;
    for (int c = 0; c < KT; c++) {
        if (c + 2 < KT) cp_wait<1>(); else cp_wait<0>();
        __syncthreads();

        if (c + 2 < KT) {
            int ns = stage + 2; if (ns >= 3) ns -= 3;
            const uint32_t sb = (uint32_t)(ns * 16384);
#pragma unroll
            for (int i = 0; i < 4; i++) {
                cpasync16(uA + sb + so[i], gA + (c + 2) * 64 + i * 8);
                cpasync16(uB + sb + so[i], gB + (c + 2) * 64 + i * 8);
            }
            cp_commit();
        }

        const char* as_ = (const char*)(As + stage * 8192);
        const char* bs_ = (const char*)(Bs + stage * 8192);
#pragma unroll
        for (int kk = 0; kk < 4; kk++) {
            const int c0o = ck[2 * kk];
            const int c1o = ck[2 * kk + 1];
            uint32_t af[2][4], bf[8][2];
#pragma unroll
            for (int im = 0; im < 2; im++) {
                const int ba = baseA0 + im * 2048;
                af[im][0] = *(const uint32_t*)(as_ + ba +        c0o);
                af[im][1] = *(const uint32_t*)(as_ + ba + 1024 + c0o);
                af[im][2] = *(const uint32_t*)(as_ + ba +        c1o);
                af[im][3] = *(const uint32_t*)(as_ + ba + 1024 + c1o);
            }
#pragma unroll
            for (int in_ = 0; in_ < 8; in_++) {
                bf[in_][0] = *(const uint32_t*)(bs_ + baseB0 + in_ * 1024 + c0o);
                bf[in_][1] = *(const uint32_t*)(bs_ + baseB0 + in_ * 1024 + c1o);
            }
#pragma unroll
            for (int im = 0; im < 2; im++)
#pragma unroll
                for (int in_ = 0; in_ < 8; in_++)
                    mma16(acc[im][in_], af[im], bf[in_]);
        }
        __syncthreads();
        if (++stage == 3) stage = 0;
    }
}

// ---------------------------------------------------------------------------
// Merged Q/K/V projection: blockIdx.z selects projection.
// ---------------------------------------------------------------------------
__global__ __launch_bounds__(256, 2)
void qkv_kernel(const float* __restrict__ bq, const float* __restrict__ bk,
                const float* __restrict__ bv) {
    const int z = blockIdx.z;
    const __half* A    = (z == 0) ? g_rq  : (z == 1) ? g_rk  : g_rv;
    const __half* B    = (z == 0) ? g_rWq : (z == 1) ? g_rWk : g_rWv;
    const float*  bias = (z == 0) ? bq    : (z == 1) ? bk    : bv;

    const int cm = blockIdx.x * 128;
    const int cn = blockIdx.y * 128;

    float acc[2][8][4];
    gemm_mainloop_h(A, B, cm, cn, acc);

    const int tid = threadIdx.x;
    const int wid = tid >> 5, lane = tid & 31;
    const int gid = lane >> 2, tg = lane & 3;
    const int wm = (wid & 3) * 32, wn = (wid >> 2) * 64;

    __half* dstQK = (z == 0) ? g_Qh : g_Kh;

#pragma unroll
    for (int im = 0; im < 2; im++) {
#pragma unroll
        for (int in_ = 0; in_ < 8; in_++) {
            const int c0 = cn + wn + in_ * 8 + tg * 2;
            const int h = c0 >> 6, d0 = c0 & 63;
            const float b0v = bias[c0], b1v = bias[c0 + 1];
#pragma unroll
            for (int rr = 0; rr < 2; rr++) {
                const int m = cm + wm + im * 16 + gid + rr * 8;
                const int b = m >> 10, s = m & 1023;
                float v0 = acc[im][in_][rr * 2];
                float v1 = acc[im][in_][rr * 2 + 1];
                if (z == 2) {
                    g_VhT[((size_t)(b * NH + h) * HD + d0)     * SEQ + s] = __float2half_rn(v0 + b0v);
                    g_VhT[((size_t)(b * NH + h) * HD + d0 + 1) * SEQ + s] = __float2half_rn(v1 + b1v);
                } else {
                    const float* pe = g_PE + s * 64 + d0;
                    uint32_t pk = packh2(v0 + b0v + pe[0], v1 + b1v + pe[1]);
                    *reinterpret_cast<uint32_t*>(
                        dstQK + ((size_t)(b * NH + h) * SEQ + s) * HD + d0) = pk;
                }
            }
        }
    }
}

// ---------------------------------------------------------------------------
// Output projection: out = g_AO @ g_rWo^T + bo (fp32 out)
// ---------------------------------------------------------------------------
__global__ __launch_bounds__(256, 2)
void oproj_kernel(const float* __restrict__ bo, float* __restrict__ out) {
    const int cm = blockIdx.x * 128;
    const int cn = blockIdx.y * 128;

    float acc[2][8][4];
    gemm_mainloop_h(g_AO, g_rWo, cm, cn, acc);

    const int tid = threadIdx.x;
    const int wid = tid >> 5, lane = tid & 31;
    const int gid = lane >> 2, tg = lane & 3;
    const int wm = (wid & 3) * 32, wn = (wid >> 2) * 64;

#pragma unroll
    for (int im = 0; im < 2; im++) {
#pragma unroll
        for (int in_ = 0; in_ < 8; in_++) {
            int r0 = cm + wm + im * 16 + gid;
            int c0 = cn + wn + in_ * 8 + tg * 2;
            out[(size_t)r0 * DM + c0]           = acc[im][in_][0] + bo[c0];
            out[(size_t)r0 * DM + c0 + 1]       = acc[im][in_][1] + bo[c0 + 1];
            out[(size_t)(r0 + 8) * DM + c0]     = acc[im][in_][2] + bo[c0];
            out[(size_t)(r0 + 8) * DM + c0 + 1] = acc[im][in_][3] + bo[c0 + 1];
        }
    }
}

// ---------------------------------------------------------------------------
// Flash attention (fp16). 64-thread CTAs (2 warps), each warp owns 32 q-rows.
// Grid (16,64) = 1024 CTAs -> smooth waves, ~4 CTAs/SM (reg-bound).
// QK C-frag maps natively to PV A-frag. Softmax via folded ex2.
// ---------------------------------------------------------------------------
#define SM_C 0.18033688011112042f   // 0.125 * log2(e)

__global__ __launch_bounds__(64)
void flash_kernel() {
    __shared__ __half Ks[2][4096];
    __shared__ __half Vs[2][4096];

    const int tid  = threadIdx.x;
    const int lane = tid & 31;
    const int w    = tid >> 5;       // 0..1
    const int gid  = lane >> 2;
    const int tg   = lane & 3;
    const int qt   = blockIdx.x;
    const int bh   = blockIdx.y;

    const __half* Qb = g_Qh  + (size_t)bh * (SEQ * HD);
    const __half* Kb = g_Kh  + (size_t)bh * (SEQ * HD);
    const __half* Vb = g_VhT + (size_t)bh * (HD * SEQ);

    // Q fragments: two m16 tiles per warp (rows qt*64 + w*32 + {0..31})
    uint32_t qf[2][4][4];
    {
#pragma unroll
        for (int im = 0; im < 2; im++) {
            const __half* r0 = Qb + (size_t)(qt * 64 + w * 32 + im * 16 + gid) * HD + 2 * tg;
            const __half* r1 = r0 + 8 * HD;
#pragma unroll
            for (int kk = 0; kk < 4; kk++) {
                qf[im][kk][0] = *(const uint32_t*)(r0 + kk * 16);
                qf[im][kk][1] = *(const uint32_t*)(r1 + kk * 16);
                qf[im][kk][2] = *(const uint32_t*)(r0 + kk * 16 + 8);
                qf[im][kk][3] = *(const uint32_t*)(r1 + kk * 16 + 8);
            }
        }
    }

    // cp.async staging: 64 thr -> one full 128B row per thread (8 chunks)
    const int r = tid;               // row 0..63
    const uint32_t ksm = (uint32_t)__cvta_generic_to_shared(Ks) + r * 128;
    const uint32_t vsm = (uint32_t)__cvta_generic_to_shared(Vs) + r * 128;
    uint32_t co[8];
#pragma unroll
    for (int i = 0; i < 8; i++) co[i] = (uint32_t)(((i ^ (r & 7)) << 4));
    const __half* kg = Kb + (size_t)r * HD;
    const __half* vg = Vb + (size_t)r * SEQ;

    // prologue: stage tile 0 into buf 0
#pragma unroll
    for (int i = 0; i < 8; i++) {
        cpasync16(ksm + co[i], kg + i * 8);
        cpasync16(vsm + co[i], vg + i * 8);
    }
    cp_commit();
    cp_wait<0>();
    __syncthreads();

    float mx[4] = {-1e30f, -1e30f, -1e30f, -1e30f};
    float li[4] = {0.f, 0.f, 0.f, 0.f};
    float ao[2][8][4];
#pragma unroll
    for (int im = 0; im < 2; im++)
#pragma unroll
        for (int t = 0; t < 8; t++)
#pragma unroll
            for (int j = 0; j < 4; j++) ao[im][t][j] = 0.f;

    const int rbase = gid * 128 + tg * 4;
    int ckv[8];
#pragma unroll
    for (int j = 0; j < 8; j++) ckv[j] = ((j ^ gid) << 4);

    for (int kt = 0; kt < 16; kt++) {
        const int buf = kt & 1;
        if (kt < 15) {
            const __half* kgn = kg + (size_t)(kt + 1) * 64 * HD;
            const __half* vgn = vg + (kt + 1) * 64;
            const uint32_t kd = ksm + (uint32_t)((buf ^ 1) * 8192);
            const uint32_t vd = vsm + (uint32_t)((buf ^ 1) * 8192);
#pragma unroll
            for (int i = 0; i < 8; i++) {
                cpasync16(kd + co[i], kgn + i * 8);
                cpasync16(vd + co[i], vgn + i * 8);
            }
            cp_commit();
        }

        const char* ks = (const char*)Ks[buf];
        const char* vs = (const char*)Vs[buf];

        // S = Q @ K^T (raw scores)
        float s[2][8][4];
#pragma unroll
        for (int im = 0; im < 2; im++)
#pragma unroll
            for (int t = 0; t < 8; t++)
#pragma unroll
                for (int j = 0; j < 4; j++) s[im][t][j] = 0.f;

#pragma unroll
        for (int kk = 0; kk < 4; kk++) {
            const int c0o = ckv[2 * kk];
            const int c1o = ckv[2 * kk + 1];
#pragma unroll
            for (int tn = 0; tn < 8; tn++) {
                uint32_t bb[2];
                bb[0] = *(const uint32_t*)(ks + tn * 1024 + rbase + c0o);
                bb[1] = *(const uint32_t*)(ks + tn * 1024 + rbase + c1o);
                mma16(s[0][tn], qf[0][kk], bb);
                mma16(s[1][tn], qf[1][kk], bb);
            }
        }

        // row max over raw scores
        float t0[4] = {-1e30f, -1e30f, -1e30f, -1e30f};
#pragma unroll
        for (int im = 0; im < 2; im++)
#pragma unroll
            for (int tn = 0; tn < 8; tn++) {
                t0[im*2]   = fmaxf(t0[im*2],   fmaxf(s[im][tn][0], s[im][tn][1]));
                t0[im*2+1] = fmaxf(t0[im*2+1], fmaxf(s[im][tn][2], s[im][tn][3]));
            }
#pragma unroll
        for (int rr = 0; rr < 4; rr++) {
            t0[rr] = fmaxf(t0[rr], __shfl_xor_sync(0xffffffffu, t0[rr], 1));
            t0[rr] = fmaxf(t0[rr], __shfl_xor_sync(0xffffffffu, t0[rr], 2));
        }

        float mn[4], al[4], nmc[4], rs[4] = {0.f, 0.f, 0.f, 0.f};
#pragma unroll
        for (int rr = 0; rr < 4; rr++) {
            mn[rr] = fmaxf(mx[rr], t0[rr]);
            al[rr] = ex2((mx[rr] - mn[rr]) * SM_C);
            nmc[rr] = -mn[rr] * SM_C;
        }

#pragma unroll
        for (int im = 0; im < 2; im++)
#pragma unroll
            for (int tn = 0; tn < 8; tn++) {
                s[im][tn][0] = ex2(fmaf(s[im][tn][0], SM_C, nmc[im*2]));
                s[im][tn][1] = ex2(fmaf(s[im][tn][1], SM_C, nmc[im*2]));
                s[im][tn][2] = ex2(fmaf(s[im][tn][2], SM_C, nmc[im*2+1]));
                s[im][tn][3] = ex2(fmaf(s[im][tn][3], SM_C, nmc[im*2+1]));
                rs[im*2]   += s[im][tn][0] + s[im][tn][1];
                rs[im*2+1] += s[im][tn][2] + s[im][tn][3];
            }
#pragma unroll
        for (int rr = 0; rr < 4; rr++) {
            rs[rr] += __shfl_xor_sync(0xffffffffu, rs[rr], 1);
            rs[rr] += __shfl_xor_sync(0xffffffffu, rs[rr], 2);
            li[rr] = li[rr] * al[rr] + rs[rr];
            mx[rr] = mn[rr];
        }
#pragma unroll
        for (int im = 0; im < 2; im++)
#pragma unroll
            for (int tn = 0; tn < 8; tn++) {
                ao[im][tn][0] *= al[im*2];   ao[im][tn][1] *= al[im*2];
                ao[im][tn][2] *= al[im*2+1]; ao[im][tn][3] *= al[im*2+1];
            }

        // O += P @ V (C-frag -> fp16 A-frag natively)
#pragma unroll
        for (int kc = 0; kc < 4; kc++) {
            uint32_t pa0[4] = { packh2(s[0][2*kc][0],   s[0][2*kc][1]),
                                packh2(s[0][2*kc][2],   s[0][2*kc][3]),
                                packh2(s[0][2*kc+1][0], s[0][2*kc+1][1]),
                                packh2(s[0][2*kc+1][2], s[0][2*kc+1][3]) };
            uint32_t pa1[4] = { packh2(s[1][2*kc][0],   s[1][2*kc][1]),
                                packh2(s[1][2*kc][2],   s[1][2*kc][3]),
                                packh2(s[1][2*kc+1][0], s[1][2*kc+1][1]),
                                packh2(s[1][2*kc+1][2], s[1][2*kc+1][3]) };
            const int c0o = ckv[2 * kc];
            const int c1o = ckv[2 * kc + 1];
#pragma unroll
            for (int tn = 0; tn < 8; tn++) {
                uint32_t bb[2];
                bb[0] = *(const uint32_t*)(vs + tn * 1024 + rbase + c0o);
                bb[1] = *(const uint32_t*)(vs + tn * 1024 + rbase + c1o);
                mma16(ao[0][tn], pa0, bb);
                mma16(ao[1][tn], pa1, bb);
            }
        }

        cp_wait<0>();
        __syncthreads();
    }

    // normalize + fp16 store to g_AO [B,S,D]
    int b = bh >> 4, h = bh & 15;
#pragma unroll
    for (int im = 0; im < 2; im++) {
        float i0 = 1.f / li[im*2], i1 = 1.f / li[im*2+1];
        size_t srow = (size_t)qt * 64 + w * 32 + im * 16 + gid;
        __half* O0 = g_AO + ((size_t)b * SEQ + srow) * DM + h * HD + tg * 2;
        __half* O1 = O0 + (size_t)8 * DM;
#pragma unroll
        for (int tn = 0; tn < 8; tn++) {
            *reinterpret_cast<uint32_t*>(O0 + tn * 8) =
                packh2(ao[im][tn][0] * i0, ao[im][tn][1] * i0);
            *reinterpret_cast<uint32_t*>(O1 + tn * 8) =
                packh2(ao[im][tn][2] * i1, ao[im][tn][3] * i1);
        }
    }
}

// ---------------------------------------------------------------------------
extern "C" void kernel_launch(void* const* d_in, const int* in_sizes, int n_in,
                              void* d_out, int out_size) {
    const float* q  = (const float*)d_in[0];
    const float* k  = (const float*)d_in[1];
    const float* v  = (const float*)d_in[2];
    const float* Wq = (const float*)d_in[3];
    const float* bq = (const float*)d_in[4];
    const float* Wk = (const float*)d_in[5];
    const float* bk = (const float*)d_in[6];
    const float* Wv = (const float*)d_in[7];
    const float* bv = (const float*)d_in[8];
    const float* Wo = (const float*)d_in[9];
    const float* bo = (const float*)d_in[10];
    float* out = (float*)d_out;

    cudaFuncSetAttribute(qkv_kernel, cudaFuncAttributeMaxDynamicSharedMemorySize,
                         GEMM_SMEM_BYTES);
    cudaFuncSetAttribute(oproj_kernel, cudaFuncAttributeMaxDynamicSharedMemorySize,
                         GEMM_SMEM_BYTES);

    prep_kernel<<<dim3(4096, 8), 256>>>((const float4*)q, (const float4*)k,
                                        (const float4*)v, (const float4*)Wq,
                                        (const float4*)Wk, (const float4*)Wv,
                                        (const float4*)Wo);

    qkv_kernel<<<dim3(32, 8, 3), 256, GEMM_SMEM_BYTES>>>(bq, bk, bv);
    flash_kernel<<<dim3(16, 64), 64>>>();
    oproj_kernel<<<dim3(32, 8), 256, GEMM_SMEM_BYTES>>>(bo, out);
}

// round 17
// speedup vs baseline: 1.1768x; 1.1768x over previous
#include <cuda_runtime.h>
#include <cuda_fp16.h>
#include <math.h>
#include <stdint.h>

#define BATCH 4
#define SEQ   1024
#define DM    1024
#define NH    16
#define HD    64
#define BH    (BATCH*NH)

// Scratch (device globals: allocation-free per harness rules). All fp16.
__device__ __half g_rq [BATCH*SEQ*DM];
__device__ __half g_rk [BATCH*SEQ*DM];
__device__ __half g_rv [BATCH*SEQ*DM];
__device__ __half g_rWq[DM*DM];
__device__ __half g_rWk[DM*DM];
__device__ __half g_rWv[DM*DM];
__device__ __half g_rWo[DM*DM];
__device__ __half g_Qh [BATCH*NH*SEQ*HD];   // [B,H,S,hd]
__device__ __half g_Kh [BATCH*NH*SEQ*HD];   // [B,H,S,hd]
__device__ __half g_Vh [BATCH*NH*SEQ*HD];   // [B,H,S,hd]  (natural, like K)
__device__ __half g_AO [BATCH*SEQ*DM];      // [B,S,D]
__device__ float  g_PE [SEQ*HD];            // fp32 PE table

// ---------------------------------------------------------------------------
__device__ __forceinline__ uint32_t packh2(float a, float b) {
    __half2 h = __floats2half2_rn(a, b);
    return *reinterpret_cast<uint32_t*>(&h);
}

__device__ __forceinline__ float ex2(float x) {
    float r;
    asm("ex2.approx.f32 %0, %1;" : "=f"(r) : "f"(x));
    return r;
}

__device__ __forceinline__ void mma16(float* c, const uint32_t* a, const uint32_t* b) {
    asm volatile(
        "mma.sync.aligned.m16n8k16.row.col.f32.f16.f16.f32 "
        "{%0,%1,%2,%3},{%4,%5,%6,%7},{%8,%9},{%0,%1,%2,%3};"
        : "+f"(c[0]), "+f"(c[1]), "+f"(c[2]), "+f"(c[3])
        : "r"(a[0]), "r"(a[1]), "r"(a[2]), "r"(a[3]), "r"(b[0]), "r"(b[1]));
}

__device__ __forceinline__ void ldmatrix_x2_trans(uint32_t& b0, uint32_t& b1, uint32_t addr) {
    asm volatile("ldmatrix.sync.aligned.m8n8.x2.trans.shared.b16 {%0,%1}, [%2];"
                 : "=r"(b0), "=r"(b1) : "r"(addr));
}

__device__ __forceinline__ void cpasync16(uint32_t dst, const void* src) {
    asm volatile("cp.async.cg.shared.global [%0], [%1], 16;" :: "r"(dst), "l"(src));
}
__device__ __forceinline__ void cp_commit() { asm volatile("cp.async.commit_group;"); }
template<int N>
__device__ __forceinline__ void cp_wait() {
    asm volatile("cp.async.wait_group %0;" :: "n"(N));
}

// ---------------------------------------------------------------------------
// Prep: round all GEMM operands to fp16 + build PE table. grid (4096, 8)
// ---------------------------------------------------------------------------
__global__ void prep_kernel(const float4* __restrict__ q, const float4* __restrict__ k,
                            const float4* __restrict__ v,
                            const float4* __restrict__ wq, const float4* __restrict__ wk,
                            const float4* __restrict__ wv, const float4* __restrict__ wo) {
    int i = blockIdx.x * blockDim.x + threadIdx.x;
    int z = blockIdx.y;
    if (z == 7) {
        int idx = i * 4;
        if (idx >= SEQ * HD) return;
        int s = idx >> 6;
        float4 r;
        float* rp = &r.x;
#pragma unroll
        for (int j = 0; j < 4; j++) {
            int d = (idx + j) & 63;
            int de = d & ~1;
            float div = expf(-(float)de * 0.14391156831212787f);   // ln(10000)/64
            float ang = (float)s * div;
            rp[j] = (d & 1) ? cosf(ang) : sinf(ang);
        }
        *(float4*)(g_PE + idx) = r;
        return;
    }
    const float4* src;
    __half* dst;
    int n4;
    switch (z) {
        case 0: src = q;  dst = g_rq;  n4 = BATCH*SEQ*DM/4; break;
        case 1: src = k;  dst = g_rk;  n4 = BATCH*SEQ*DM/4; break;
        case 2: src = v;  dst = g_rv;  n4 = BATCH*SEQ*DM/4; break;
        case 3: src = wq; dst = g_rWq; n4 = DM*DM/4; break;
        case 4: src = wk; dst = g_rWk; n4 = DM*DM/4; break;
        case 5: src = wv; dst = g_rWv; n4 = DM*DM/4; break;
        default:src = wo; dst = g_rWo; n4 = DM*DM/4; break;
    }
    if (i >= n4) return;
    float4 a = src[i];
    uint2 u;
    u.x = packh2(a.x, a.y);
    u.y = packh2(a.z, a.w);
    *reinterpret_cast<uint2*>(dst + 4 * i) = u;
}

// ---------------------------------------------------------------------------
// NT GEMM mainloop (fp16): acc = A[128,:] @ B[128,:]^T over K=1024.
// CTA 128x128, K-chunk 64 halfs (128B rows), 3-stage cp.async ring (16 iters,
// single barrier per iteration — trailing barrier proven redundant).
// 8 warps 4(m)x2(n), warp tile 32x64, mma m16n8k16.
// 128B rows, 16B-chunk XOR key row&7 -> fragment LDS.32 conflict-free.
// Dynamic smem: A 3x16KB | B 3x16KB = 96KB.
// ---------------------------------------------------------------------------
#define GEMM_SMEM_BYTES 98304

__device__ __forceinline__ void gemm_mainloop_h(
    const __half* __restrict__ A, const __half* __restrict__ B,
    int cm, int cn, float acc[2][8][4])
{
    extern __shared__ __half dsm[];
    __half* As = dsm;               // 3 x 8192 halfs
    __half* Bs = dsm + 3 * 8192;

    constexpr int KT = 16;   // 1024 / 64

    const int tid = threadIdx.x;
    const int r   = tid >> 1;          // 0..127
    const int hh  = tid & 1;           // half of 128B row

    const __half* gA = A + (size_t)(cm + r) * 1024 + hh * 32;
    const __half* gB = B + (size_t)(cn + r) * 1024 + hh * 32;

    const uint32_t uA = (uint32_t)__cvta_generic_to_shared(As);
    const uint32_t uB = (uint32_t)__cvta_generic_to_shared(Bs);
    uint32_t so[4];
#pragma unroll
    for (int i = 0; i < 4; i++)
        so[i] = (uint32_t)(r * 128 + (((4 * hh + i) ^ (r & 7)) << 4));

    const int wid  = tid >> 5;
    const int lane = tid & 31;
    const int gid  = lane >> 2;
    const int tg   = lane & 3;
    const int wm = (wid & 3) * 32;
    const int wn = (wid >> 2) * 64;

    int ck[8];
#pragma unroll
    for (int j = 0; j < 8; j++) ck[j] = ((j ^ gid) << 4);
    const int baseA0 = (wm + gid) * 128 + tg * 4;
    const int baseB0 = (wn + gid) * 128 + tg * 4;

#pragma unroll
    for (int i = 0; i < 2; i++)
#pragma unroll
        for (int j = 0; j < 8; j++)
#pragma unroll
            for (int l = 0; l < 4; l++) acc[i][j][l] = 0.f;

    // prologue: stages 0,1
#pragma unroll
    for (int s = 0; s < 2; s++) {
        const uint32_t sb = (uint32_t)(s * 16384);
#pragma unroll
        for (int i = 0; i < 4; i++) {
            cpasync16(uA + sb + so[i], gA + s * 64 + i * 8);
            cpasync16(uB + sb + so[i], gB + s * 64 + i * 8);
        }
        cp_commit();
    }

    int stage = 0;
    for (int c = 0; c < KT; c++) {
        if (c + 2 < KT) cp_wait<1>(); else cp_wait<0>();
        __syncthreads();   // separates prior compute from the stage overwrite below

        if (c + 2 < KT) {
            int ns = stage + 2; if (ns >= 3) ns -= 3;
            const uint32_t sb = (uint32_t)(ns * 16384);
#pragma unroll
            for (int i = 0; i < 4; i++) {
                cpasync16(uA + sb + so[i], gA + (c + 2) * 64 + i * 8);
                cpasync16(uB + sb + so[i], gB + (c + 2) * 64 + i * 8);
            }
            cp_commit();
        }

        const char* as_ = (const char*)(As + stage * 8192);
        const char* bs_ = (const char*)(Bs + stage * 8192);
#pragma unroll
        for (int kk = 0; kk < 4; kk++) {
            const int c0o = ck[2 * kk];
            const int c1o = ck[2 * kk + 1];
            uint32_t af[2][4], bf[8][2];
#pragma unroll
            for (int im = 0; im < 2; im++) {
                const int ba = baseA0 + im * 2048;
                af[im][0] = *(const uint32_t*)(as_ + ba +        c0o);
                af[im][1] = *(const uint32_t*)(as_ + ba + 1024 + c0o);
                af[im][2] = *(const uint32_t*)(as_ + ba +        c1o);
                af[im][3] = *(const uint32_t*)(as_ + ba + 1024 + c1o);
            }
#pragma unroll
            for (int in_ = 0; in_ < 8; in_++) {
                bf[in_][0] = *(const uint32_t*)(bs_ + baseB0 + in_ * 1024 + c0o);
                bf[in_][1] = *(const uint32_t*)(bs_ + baseB0 + in_ * 1024 + c1o);
            }
#pragma unroll
            for (int im = 0; im < 2; im++)
#pragma unroll
                for (int in_ = 0; in_ < 8; in_++)
                    mma16(acc[im][in_], af[im], bf[in_]);
        }
        if (++stage == 3) stage = 0;
    }
}

// ---------------------------------------------------------------------------
// Merged Q/K/V projection: blockIdx.z selects projection.
// ALL three outputs stored naturally [B,H,S,hd] with packed half2 (coalesced);
// V transpose handled in flash via ldmatrix.trans.
// ---------------------------------------------------------------------------
__global__ __launch_bounds__(256, 2)
void qkv_kernel(const float* __restrict__ bq, const float* __restrict__ bk,
                const float* __restrict__ bv) {
    const int z = blockIdx.z;
    const __half* A    = (z == 0) ? g_rq  : (z == 1) ? g_rk  : g_rv;
    const __half* B    = (z == 0) ? g_rWq : (z == 1) ? g_rWk : g_rWv;
    const float*  bias = (z == 0) ? bq    : (z == 1) ? bk    : bv;

    const int cm = blockIdx.x * 128;
    const int cn = blockIdx.y * 128;

    float acc[2][8][4];
    gemm_mainloop_h(A, B, cm, cn, acc);

    const int tid = threadIdx.x;
    const int wid = tid >> 5, lane = tid & 31;
    const int gid = lane >> 2, tg = lane & 3;
    const int wm = (wid & 3) * 32, wn = (wid >> 2) * 64;

    __half* dst = (z == 0) ? g_Qh : (z == 1) ? g_Kh : g_Vh;
    const bool addPE = (z != 2);

#pragma unroll
    for (int im = 0; im < 2; im++) {
#pragma unroll
        for (int in_ = 0; in_ < 8; in_++) {
            const int c0 = cn + wn + in_ * 8 + tg * 2;
            const int h = c0 >> 6, d0 = c0 & 63;
            const float b0v = bias[c0], b1v = bias[c0 + 1];
#pragma unroll
            for (int rr = 0; rr < 2; rr++) {
                const int m = cm + wm + im * 16 + gid + rr * 8;
                const int b = m >> 10, s = m & 1023;
                float v0 = acc[im][in_][rr * 2]     + b0v;
                float v1 = acc[im][in_][rr * 2 + 1] + b1v;
                if (addPE) {
                    const float* pe = g_PE + s * 64 + d0;
                    v0 += pe[0];
                    v1 += pe[1];
                }
                *reinterpret_cast<uint32_t*>(
                    dst + ((size_t)(b * NH + h) * SEQ + s) * HD + d0) = packh2(v0, v1);
            }
        }
    }
}

// ---------------------------------------------------------------------------
// Output projection: out = g_AO @ g_rWo^T + bo (fp32 out)
// ---------------------------------------------------------------------------
__global__ __launch_bounds__(256, 2)
void oproj_kernel(const float* __restrict__ bo, float* __restrict__ out) {
    const int cm = blockIdx.x * 128;
    const int cn = blockIdx.y * 128;

    float acc[2][8][4];
    gemm_mainloop_h(g_AO, g_rWo, cm, cn, acc);

    const int tid = threadIdx.x;
    const int wid = tid >> 5, lane = tid & 31;
    const int gid = lane >> 2, tg = lane & 3;
    const int wm = (wid & 3) * 32, wn = (wid >> 2) * 64;

#pragma unroll
    for (int im = 0; im < 2; im++) {
#pragma unroll
        for (int in_ = 0; in_ < 8; in_++) {
            int r0 = cm + wm + im * 16 + gid;
            int c0 = cn + wn + in_ * 8 + tg * 2;
            out[(size_t)r0 * DM + c0]           = acc[im][in_][0] + bo[c0];
            out[(size_t)r0 * DM + c0 + 1]       = acc[im][in_][1] + bo[c0 + 1];
            out[(size_t)(r0 + 8) * DM + c0]     = acc[im][in_][2] + bo[c0];
            out[(size_t)(r0 + 8) * DM + c0 + 1] = acc[im][in_][3] + bo[c0 + 1];
        }
    }
}

// ---------------------------------------------------------------------------
// Flash attention (fp16). 128 thr, warp owns 32 q-rows (two m16 tiles) —
// proven R13 shape. V stored NATURALLY [s][d]; PV B-frags produced by
// ldmatrix.x2.trans (transpose for free, fewer LDS). K path unchanged.
// Softmax via folded ex2 (C = 0.125*log2e) on raw scores.
// ---------------------------------------------------------------------------
#define SM_C 0.18033688011112042f   // 0.125 * log2(e)

__global__ __launch_bounds__(128, 2)
void flash_kernel() {
    __shared__ __half Ks[2][4096];
    __shared__ __half Vs[2][4096];

    const int tid  = threadIdx.x;
    const int lane = tid & 31;
    const int w    = tid >> 5;       // 0..3
    const int gid  = lane >> 2;
    const int tg   = lane & 3;
    const int qt   = blockIdx.x;
    const int bh   = blockIdx.y;

    const __half* Qb = g_Qh + (size_t)bh * (SEQ * HD);
    const __half* Kb = g_Kh + (size_t)bh * (SEQ * HD);
    const __half* Vb = g_Vh + (size_t)bh * (SEQ * HD);

    uint32_t qf[2][4][4];
    {
#pragma unroll
        for (int im = 0; im < 2; im++) {
            const __half* r0 = Qb + (size_t)(qt * 128 + w * 32 + im * 16 + gid) * HD + 2 * tg;
            const __half* r1 = r0 + 8 * HD;
#pragma unroll
            for (int kk = 0; kk < 4; kk++) {
                qf[im][kk][0] = *(const uint32_t*)(r0 + kk * 16);
                qf[im][kk][1] = *(const uint32_t*)(r1 + kk * 16);
                qf[im][kk][2] = *(const uint32_t*)(r0 + kk * 16 + 8);
                qf[im][kk][3] = *(const uint32_t*)(r1 + kk * 16 + 8);
            }
        }
    }

    // cp.async staging: row r = tid>>1 (0..63), 4x16B chunks per thread.
    // K and V tiles are both [row=s][64 halfs], swizzle key r&7.
    const int r  = tid >> 1;
    const int hf = tid & 1;
    const uint32_t ksm = (uint32_t)__cvta_generic_to_shared(Ks) + r * 128;
    const uint32_t vsm = (uint32_t)__cvta_generic_to_shared(Vs) + r * 128;
    uint32_t co[4];
#pragma unroll
    for (int i = 0; i < 4; i++) co[i] = (uint32_t)((((4 * hf + i) ^ (r & 7)) << 4));
    const __half* kg = Kb + (size_t)r * HD + hf * 32;
    const __half* vg = Vb + (size_t)r * HD + hf * 32;

#pragma unroll
    for (int i = 0; i < 4; i++) {
        cpasync16(ksm + co[i], kg + i * 8);
        cpasync16(vsm + co[i], vg + i * 8);
    }
    cp_commit();
    cp_wait<0>();
    __syncthreads();

    float mx[4] = {-1e30f, -1e30f, -1e30f, -1e30f};
    float li[4] = {0.f, 0.f, 0.f, 0.f};
    float ao[2][8][4];
#pragma unroll
    for (int im = 0; im < 2; im++)
#pragma unroll
        for (int t = 0; t < 8; t++)
#pragma unroll
            for (int j = 0; j < 4; j++) ao[im][t][j] = 0.f;

    const int rbase = gid * 128 + tg * 4;
    int ckv[8];
#pragma unroll
    for (int j = 0; j < 8; j++) ckv[j] = ((j ^ gid) << 4);

    // ldmatrix.x2.trans lane addressing for V: lanes 0-15 supply rows
    // k = kc*16 + lm (lm = lane&15) of the V tile; column block = tn (16B chunk),
    // swizzled by (k&7) = (lm&7).
    const int lm    = lane & 15;
    const int vmask = lm & 7;
    const uint32_t vs0 = (uint32_t)__cvta_generic_to_shared(Vs);

    for (int kt = 0; kt < 16; kt++) {
        const int buf = kt & 1;
        if (kt < 15) {
            const __half* kgn = kg + (size_t)(kt + 1) * 64 * HD;
            const __half* vgn = vg + (size_t)(kt + 1) * 64 * HD;
            const uint32_t kd = ksm + (uint32_t)((buf ^ 1) * 8192);
            const uint32_t vd = vsm + (uint32_t)((buf ^ 1) * 8192);
#pragma unroll
            for (int i = 0; i < 4; i++) {
                cpasync16(kd + co[i], kgn + i * 8);
                cpasync16(vd + co[i], vgn + i * 8);
            }
            cp_commit();
        }

        const char* ks = (const char*)Ks[buf];
        const uint32_t vsb = vs0 + (uint32_t)(buf * 8192);

        // S = Q @ K^T (raw scores)
        float s[2][8][4];
#pragma unroll
        for (int im = 0; im < 2; im++)
#pragma unroll
            for (int t = 0; t < 8; t++)
#pragma unroll
                for (int j = 0; j < 4; j++) s[im][t][j] = 0.f;

#pragma unroll
        for (int kk = 0; kk < 4; kk++) {
            const int c0o = ckv[2 * kk];
            const int c1o = ckv[2 * kk + 1];
#pragma unroll
            for (int tn = 0; tn < 8; tn++) {
                uint32_t bb[2];
                bb[0] = *(const uint32_t*)(ks + tn * 1024 + rbase + c0o);
                bb[1] = *(const uint32_t*)(ks + tn * 1024 + rbase + c1o);
                mma16(s[0][tn], qf[0][kk], bb);
                mma16(s[1][tn], qf[1][kk], bb);
            }
        }

        // row max over raw scores
        float t0[4] = {-1e30f, -1e30f, -1e30f, -1e30f};
#pragma unroll
        for (int im = 0; im < 2; im++)
#pragma unroll
            for (int tn = 0; tn < 8; tn++) {
                t0[im*2]   = fmaxf(t0[im*2],   fmaxf(s[im][tn][0], s[im][tn][1]));
                t0[im*2+1] = fmaxf(t0[im*2+1], fmaxf(s[im][tn][2], s[im][tn][3]));
            }
#pragma unroll
        for (int rr = 0; rr < 4; rr++) {
            t0[rr] = fmaxf(t0[rr], __shfl_xor_sync(0xffffffffu, t0[rr], 1));
            t0[rr] = fmaxf(t0[rr], __shfl_xor_sync(0xffffffffu, t0[rr], 2));
        }

        float mn[4], al[4], nmc[4], rs[4] = {0.f, 0.f, 0.f, 0.f};
#pragma unroll
        for (int rr = 0; rr < 4; rr++) {
            mn[rr] = fmaxf(mx[rr], t0[rr]);
            al[rr] = ex2((mx[rr] - mn[rr]) * SM_C);
            nmc[rr] = -mn[rr] * SM_C;
        }

#pragma unroll
        for (int im = 0; im < 2; im++)
#pragma unroll
            for (int tn = 0; tn < 8; tn++) {
                s[im][tn][0] = ex2(fmaf(s[im][tn][0], SM_C, nmc[im*2]));
                s[im][tn][1] = ex2(fmaf(s[im][tn][1], SM_C, nmc[im*2]));
                s[im][tn][2] = ex2(fmaf(s[im][tn][2], SM_C, nmc[im*2+1]));
                s[im][tn][3] = ex2(fmaf(s[im][tn][3], SM_C, nmc[im*2+1]));
                rs[im*2]   += s[im][tn][0] + s[im][tn][1];
                rs[im*2+1] += s[im][tn][2] + s[im][tn][3];
            }
#pragma unroll
        for (int rr = 0; rr < 4; rr++) {
            rs[rr] += __shfl_xor_sync(0xffffffffu, rs[rr], 1);
            rs[rr] += __shfl_xor_sync(0xffffffffu, rs[rr], 2);
            li[rr] = li[rr] * al[rr] + rs[rr];
            mx[rr] = mn[rr];
        }
#pragma unroll
        for (int im = 0; im < 2; im++)
#pragma unroll
            for (int tn = 0; tn < 8; tn++) {
                ao[im][tn][0] *= al[im*2];   ao[im][tn][1] *= al[im*2];
                ao[im][tn][2] *= al[im*2+1]; ao[im][tn][3] *= al[im*2+1];
            }

        // O += P @ V : B-frags via ldmatrix.x2.trans from natural-layout V tile
#pragma unroll
        for (int kc = 0; kc < 4; kc++) {
            uint32_t pa0[4] = { packh2(s[0][2*kc][0],   s[0][2*kc][1]),
                                packh2(s[0][2*kc][2],   s[0][2*kc][3]),
                                packh2(s[0][2*kc+1][0], s[0][2*kc+1][1]),
                                packh2(s[0][2*kc+1][2], s[0][2*kc+1][3]) };
            uint32_t pa1[4] = { packh2(s[1][2*kc][0],   s[1][2*kc][1]),
                                packh2(s[1][2*kc][2],   s[1][2*kc][3]),
                                packh2(s[1][2*kc+1][0], s[1][2*kc+1][1]),
                                packh2(s[1][2*kc+1][2], s[1][2*kc+1][3]) };
            const uint32_t a0 = vsb + (uint32_t)((kc * 16 + lm) * 128);
#pragma unroll
            for (int tn = 0; tn < 8; tn++) {
                uint32_t bb[2];
                ldmatrix_x2_trans(bb[0], bb[1], a0 + (uint32_t)(((tn ^ vmask)) << 4));
                mma16(ao[0][tn], pa0, bb);
                mma16(ao[1][tn], pa1, bb);
            }
        }

        cp_wait<0>();
        __syncthreads();
    }

    // normalize + fp16 store to g_AO [B,S,D]
    int b = bh >> 4, h = bh & 15;
#pragma unroll
    for (int im = 0; im < 2; im++) {
        float i0 = 1.f / li[im*2], i1 = 1.f / li[im*2+1];
        size_t srow = (size_t)qt * 128 + w * 32 + im * 16 + gid;
        __half* O0 = g_AO + ((size_t)b * SEQ + srow) * DM + h * HD + tg * 2;
        __half* O1 = O0 + (size_t)8 * DM;
#pragma unroll
        for (int tn = 0; tn < 8; tn++) {
            *reinterpret_cast<uint32_t*>(O0 + tn * 8) =
                packh2(ao[im][tn][0] * i0, ao[im][tn][1] * i0);
            *reinterpret_cast<uint32_t*>(O1 + tn * 8) =
                packh2(ao[im][tn][2] * i1, ao[im][tn][3] * i1);
        }
    }
}

// ---------------------------------------------------------------------------
extern "C" void kernel_launch(void* const* d_in, const int* in_sizes, int n_in,
                              void* d_out, int out_size) {
    const float* q  = (const float*)d_in[0];
    const float* k  = (const float*)d_in[1];
    const float* v  = (const float*)d_in[2];
    const float* Wq = (const float*)d_in[3];
    const float* bq = (const float*)d_in[4];
    const float* Wk = (const float*)d_in[5];
    const float* bk = (const float*)d_in[6];
    const float* Wv = (const float*)d_in[7];
    const float* bv = (const float*)d_in[8];
    const float* Wo = (const float*)d_in[9];
    const float* bo = (const float*)d_in[10];
    float* out = (float*)d_out;

    cudaFuncSetAttribute(qkv_kernel, cudaFuncAttributeMaxDynamicSharedMemorySize,
                         GEMM_SMEM_BYTES);
    cudaFuncSetAttribute(oproj_kernel, cudaFuncAttributeMaxDynamicSharedMemorySize,
                         GEMM_SMEM_BYTES);

    prep_kernel<<<dim3(4096, 8), 256>>>((const float4*)q, (const float4*)k,
                                        (const float4*)v, (const float4*)Wq,
                                        (const float4*)Wk, (const float4*)Wv,
                                        (const float4*)Wo);

    qkv_kernel<<<dim3(32, 8, 3), 256, GEMM_SMEM_BYTES>>>(bq, bk, bv);
    flash_kernel<<<dim3(8, 64), 128>>>();
    oproj_kernel<<<dim3(32, 8), 256, GEMM_SMEM_BYTES>>>(bo, out);
}